// round 14
// baseline (speedup 1.0000x reference)
#include <cuda_runtime.h>
#include <cuda_bf16.h>
#include <cstdint>

// Problem constants
#define BV     32000
#define EE     256
#define HH     512
#define SS     128
#define TT     64
#define BB     32
#define NSTEP  63
#define H3     1536
#define OUT_PRED (64512000LL)
#define MPRED  2016            // 63*32 rows of h

// ---------------- scratch ----------------------------------------------------
__device__ float g_encCat[4096 * 2048];   // [b*128+s][0:512)=enc@W1, [512:2048)=enc@Wx_top
__device__ float g_gxemb [NSTEP * BB * H3];
__device__ float g_h     [NSTEP * BB * HH];
__device__ float g_pp    [4 * BB * H3];   // hproj partials: vcols 0..511=h@W2, 512..1535=h@Wh_zr
__device__ float g_ph    [4 * BB * HH];   // rh@Wh3 partials
__device__ float g_score [BB * SS];
__device__ float g_z     [BB * HH];
__device__ float g_rh    [BB * HH];
__device__ float g_gx3   [BB * HH];
// bf16 hi/lo operands for the mma pred GEMM
__device__ __nv_bfloat16 g_Ah [MPRED * HH];
__device__ __nv_bfloat16 g_Al [MPRED * HH];
__device__ __nv_bfloat16 g_WTh[(long long)BV * HH];   // WoT[n][k] hi
__device__ __nv_bfloat16 g_WTl[(long long)BV * HH];   // WoT[n][k] lo

// ---------------- helpers ----------------------------------------------------
__device__ __forceinline__ unsigned long long dup2(float b) {
    unsigned long long r;
    unsigned int u = __float_as_uint(b);
    asm("mov.b64 %0, {%1, %1};" : "=l"(r) : "r"(u));
    return r;
}
__device__ __forceinline__ void fma2(unsigned long long& d,
                                     unsigned long long a,
                                     unsigned long long b) {
    asm("fma.rn.f32x2 %0, %1, %2, %3;" : "=l"(d) : "l"(a), "l"(b), "l"(d));
}
__device__ __forceinline__ float fast_tanh(float x) {
    float e = __expf(2.0f * x);
    return 1.0f - 2.0f / (e + 1.0f);
}
__device__ __forceinline__ float fast_sig(float x) {
    return 1.0f / (1.0f + __expf(-x));
}
__device__ __forceinline__ float tanh_approx(float x) {
    float y;
    asm("tanh.approx.f32 %0, %1;" : "=f"(y) : "f"(x));
    return y;
}
__device__ __forceinline__ float ppsum(int b, int col) {
    return g_pp[(0 * BB + b) * H3 + col] + g_pp[(1 * BB + b) * H3 + col]
         + g_pp[(2 * BB + b) * H3 + col] + g_pp[(3 * BB + b) * H3 + col];
}

// ---------------- generic 128x128 tiled fp32 GEMM (precompute only) ----------
// MODE 0: C=g_encCat : A=enc(4096x512),         B=[W1 | Wx_top](512x2048)
// MODE 1: C=g_gxemb  : A=emb[tok(m)](2016x256), B=Wx_bot(256x1536), +b_g
template<int MODE>
__global__ __launch_bounds__(256, 2)
void gemm_k(const float* __restrict__ A,  const float* __restrict__ W1,
            const float* __restrict__ Wx, const float* __restrict__ bias,
            const int*   __restrict__ dinp, const int* __restrict__ dtgt,
            const float* __restrict__ emb, int M, int K)
{
    __shared__ __align__(16) float As[16][132];
    __shared__ __align__(16) float Bs[16][132];

    const int tid = threadIdx.x;
    const int tx = tid & 15;
    const int ty = tid >> 4;
    const int bn = blockIdx.x, bm = blockIdx.y;

    unsigned long long acc[4][8];
#pragma unroll
    for (int i = 0; i < 4; i++)
#pragma unroll
        for (int j = 0; j < 8; j++) acc[i][j] = 0ULL;

    const int nTiles = K >> 4;
    for (int kt = 0; kt < nTiles; ++kt) {
#pragma unroll
        for (int q = 0; q < 2; q++) {
            int l = tid * 2 + q;
            int r = l >> 2;
            int cseg = l & 3;
            int rowg = bm * 128 + r; if (rowg > M - 1) rowg = M - 1;
            const float* ap;
            if (MODE == 1) {
                int t = rowg >> 5, b = rowg & 31;
                int tok = (t == 0) ? dinp[b] : dtgt[b * TT + t];
                ap = emb + (long long)tok * EE;
            } else {
                ap = A + (long long)rowg * K;
            }
            float4 v = *reinterpret_cast<const float4*>(ap + kt * 16 + cseg * 4);
            As[cseg * 4 + 0][r] = v.x; As[cseg * 4 + 1][r] = v.y;
            As[cseg * 4 + 2][r] = v.z; As[cseg * 4 + 3][r] = v.w;
            int kr = l >> 5;
            int nseg = l & 31;
            int kg = kt * 16 + kr;
            int n = bn * 128 + nseg * 4;
            const float* bp;
            if (MODE == 0) {
                bp = (n < 512) ? (W1 + (long long)kg * 512 + n)
                               : (Wx + (long long)kg * H3 + (n - 512));
            } else {
                bp = Wx + (long long)(512 + kg) * H3 + n;
            }
            *reinterpret_cast<float4*>(&Bs[kr][nseg * 4]) =
                *reinterpret_cast<const float4*>(bp);
        }
        __syncthreads();
#pragma unroll
        for (int k = 0; k < 16; k++) {
            const unsigned long long* arow =
                reinterpret_cast<const unsigned long long*>(&As[k][0]);
            unsigned long long a0 = arow[ty * 4 + 0];
            unsigned long long a1 = arow[ty * 4 + 1];
            unsigned long long a2 = arow[ty * 4 + 2];
            unsigned long long a3 = arow[ty * 4 + 3];
            float4 b0 = *reinterpret_cast<const float4*>(&Bs[k][tx * 4]);
            float4 b1 = *reinterpret_cast<const float4*>(&Bs[k][64 + tx * 4]);
            float bf[8] = {b0.x, b0.y, b0.z, b0.w, b1.x, b1.y, b1.z, b1.w};
#pragma unroll
            for (int j = 0; j < 8; j++) {
                unsigned long long dj = dup2(bf[j]);
                fma2(acc[0][j], a0, dj);
                fma2(acc[1][j], a1, dj);
                fma2(acc[2][j], a2, dj);
                fma2(acc[3][j], a3, dj);
            }
        }
        __syncthreads();
    }

    const int nA = bn * 128 + tx * 4;
    const int nB2 = nA + 64;
#pragma unroll
    for (int i2 = 0; i2 < 4; i2++) {
#pragma unroll
        for (int p = 0; p < 2; p++) {
            int m = bm * 128 + ty * 8 + i2 * 2 + p;
            if (m >= M) continue;
            float vals[8];
#pragma unroll
            for (int j = 0; j < 8; j++) {
                unsigned long long u = acc[i2][j];
                unsigned int w = (p == 0) ? (unsigned int)u
                                          : (unsigned int)(u >> 32);
                vals[j] = __uint_as_float(w);
            }
            if (MODE == 0) {
                float* cp = g_encCat + (long long)m * 2048;
                *reinterpret_cast<float4*>(cp + nA) =
                    make_float4(vals[0], vals[1], vals[2], vals[3]);
                *reinterpret_cast<float4*>(cp + nB2) =
                    make_float4(vals[4], vals[5], vals[6], vals[7]);
            } else {
                float* cp = g_gxemb + (long long)m * H3;
                float4 ba = *reinterpret_cast<const float4*>(bias + nA);
                float4 bb = *reinterpret_cast<const float4*>(bias + nB2);
                *reinterpret_cast<float4*>(cp + nA) =
                    make_float4(vals[0] + ba.x, vals[1] + ba.y,
                                vals[2] + ba.z, vals[3] + ba.w);
                *reinterpret_cast<float4*>(cp + nB2) =
                    make_float4(vals[4] + bb.x, vals[5] + bb.y,
                                vals[6] + bb.z, vals[7] + bb.w);
            }
        }
    }
}

// ---------------- per-step: hproj partials (R7-proven shape) -----------------
// grid (4 kc, 12 bc), 256 thr. vcols 0..511 -> W2, 512..1535 -> Wh[:,0:1024].
// Weights read ONCE per step; h transposed in smem; FMA2 over batch pairs.
__global__ __launch_bounds__(256)
void k_hproj(const float* __restrict__ dec_hidden,
             const float* __restrict__ W2,
             const float* __restrict__ Wh, int t)
{
    const int kc = blockIdx.x, bc = blockIdx.y;
    const int kbase = kc * 128, cbase = bc * 128;
    const int tid = threadIdx.x;
    const float* hprev = (t == 0) ? dec_hidden
                                  : g_h + (long long)(t - 1) * BB * HH;

    __shared__ float hT[128 * 34];   // hT[k*34 + b]
    for (int i = tid; i < 4096; i += 256) {
        int b = i >> 7, k = i & 127;
        hT[k * 34 + b] = hprev[b * HH + kbase + k];
    }
    __syncthreads();

    const int cq = tid & 31;             // col quad
    const int bq = tid >> 5;             // batch quad (0..7)
    const int c0 = cbase + cq * 4;
    const float* wrow; int ldw;
    if (c0 < 512) { wrow = W2 + c0;         ldw = 512; }
    else          { wrow = Wh + (c0 - 512); ldw = H3;  }

    unsigned long long acc[4][2];
#pragma unroll
    for (int c = 0; c < 4; c++) { acc[c][0] = 0ULL; acc[c][1] = 0ULL; }

#pragma unroll 4
    for (int k = 0; k < 128; k++) {
        float4 w = *reinterpret_cast<const float4*>(
            wrow + (long long)(kbase + k) * ldw);
        unsigned long long h01 =
            *reinterpret_cast<const unsigned long long*>(&hT[k * 34 + bq * 4]);
        unsigned long long h23 =
            *reinterpret_cast<const unsigned long long*>(&hT[k * 34 + bq * 4 + 2]);
        unsigned long long w0 = dup2(w.x), w1 = dup2(w.y),
                           w2 = dup2(w.z), w3 = dup2(w.w);
        fma2(acc[0][0], h01, w0); fma2(acc[0][1], h23, w0);
        fma2(acc[1][0], h01, w1); fma2(acc[1][1], h23, w1);
        fma2(acc[2][0], h01, w2); fma2(acc[2][1], h23, w2);
        fma2(acc[3][0], h01, w3); fma2(acc[3][1], h23, w3);
    }

#pragma unroll
    for (int c = 0; c < 4; c++) {
#pragma unroll
        for (int p = 0; p < 2; p++) {
            int b = bq * 4 + p * 2;
            unsigned long long u = acc[c][p];
            g_pp[(kc * BB + b)     * H3 + c0 + c] =
                __uint_as_float((unsigned int)u);
            g_pp[(kc * BB + b + 1) * H3 + c0 + c] =
                __uint_as_float((unsigned int)(u >> 32));
        }
    }
}

// ---------------- per-step: scores (reduce partials inline) ------------------
__global__ void k_score(const float* __restrict__ v_a)
{
    int b = blockIdx.y;
    int warp = threadIdx.x >> 5, lane = threadIdx.x & 31;
    int s = blockIdx.x * 8 + warp;
    __shared__ float hv[HH], vv[HH];
    for (int i = threadIdx.x; i < HH; i += 256) {
        hv[i] = ppsum(b, i);          // hW2 = sum of 4 k-partials
        vv[i] = v_a[i];
    }
    __syncthreads();
    const float* e = g_encCat + ((long long)b * SS + s) * 2048;
    float sum = 0.f;
#pragma unroll
    for (int i = 0; i < 16; i++) {
        int a = i * 32 + lane;
        sum += tanh_approx(e[a] + hv[a]) * vv[a];
    }
#pragma unroll
    for (int o = 16; o > 0; o >>= 1) sum += __shfl_xor_sync(0xffffffffu, sum, o);
    if (lane == 0) g_score[b * SS + s] = sum;
}

// ---------------- per-step: softmax + mix + gates ----------------------------
__global__ void k_attnmix(const float* __restrict__ dec_hidden, int t)
{
    int b = blockIdx.y;
    int tidx = threadIdx.x;
    int j = blockIdx.x * 128 + tidx;
    __shared__ float attn[SS];
    __shared__ float red[SS];

    float sc = g_score[b * SS + tidx];
    red[tidx] = sc; __syncthreads();
    for (int o = 64; o > 0; o >>= 1) {
        if (tidx < o) red[tidx] = fmaxf(red[tidx], red[tidx + o]);
        __syncthreads();
    }
    float mx = red[0]; __syncthreads();
    float ex = __expf(sc - mx);
    red[tidx] = ex; __syncthreads();
    for (int o = 64; o > 0; o >>= 1) {
        if (tidx < o) red[tidx] += red[tidx + o];
        __syncthreads();
    }
    attn[tidx] = ex / red[0];
    __syncthreads();

    const float* base = g_encCat + (long long)b * SS * 2048 + 512 + j;
    float acc = 0.f;
#pragma unroll 8
    for (int s = 0; s < SS; s++) acc += attn[s] * base[(long long)s * 2048];
    acc += g_gxemb[((long long)t * BB + b) * H3 + j];

    const float* h = (t == 0) ? (dec_hidden + b * HH)
                              : (g_h + ((long long)(t - 1) * BB + b) * HH);
    if (j < 512) {
        g_z[b * HH + j] = fast_sig(acc + ppsum(b, 512 + j));
    } else if (j < 1024) {
        int jj = j - 512;
        float rr = fast_sig(acc + ppsum(b, 512 + j));
        g_rh[b * HH + jj] = rr * h[jj];
    } else {
        g_gx3[b * HH + (j - 1024)] = acc;
    }
}

// ---------------- per-step: hh partials (rh @ Wh[:,1024:]) -------------------
// grid (4 kc, 4 bc), same structure as k_hproj. A = g_rh.
__global__ __launch_bounds__(256)
void k_hh(const float* __restrict__ Wh, int t)
{
    const int kc = blockIdx.x, bc = blockIdx.y;
    const int kbase = kc * 128, cbase = bc * 128;
    const int tid = threadIdx.x;

    __shared__ float hT[128 * 34];
    for (int i = tid; i < 4096; i += 256) {
        int b = i >> 7, k = i & 127;
        hT[k * 34 + b] = g_rh[b * HH + kbase + k];
    }
    __syncthreads();

    const int cq = tid & 31;
    const int bq = tid >> 5;
    const int c0 = cbase + cq * 4;
    const float* wrow = Wh + 1024 + c0;

    unsigned long long acc[4][2];
#pragma unroll
    for (int c = 0; c < 4; c++) { acc[c][0] = 0ULL; acc[c][1] = 0ULL; }

#pragma unroll 4
    for (int k = 0; k < 128; k++) {
        float4 w = *reinterpret_cast<const float4*>(
            wrow + (long long)(kbase + k) * H3);
        unsigned long long h01 =
            *reinterpret_cast<const unsigned long long*>(&hT[k * 34 + bq * 4]);
        unsigned long long h23 =
            *reinterpret_cast<const unsigned long long*>(&hT[k * 34 + bq * 4 + 2]);
        unsigned long long w0 = dup2(w.x), w1 = dup2(w.y),
                           w2 = dup2(w.z), w3 = dup2(w.w);
        fma2(acc[0][0], h01, w0); fma2(acc[0][1], h23, w0);
        fma2(acc[1][0], h01, w1); fma2(acc[1][1], h23, w1);
        fma2(acc[2][0], h01, w2); fma2(acc[2][1], h23, w2);
        fma2(acc[3][0], h01, w3); fma2(acc[3][1], h23, w3);
    }

#pragma unroll
    for (int c = 0; c < 4; c++) {
#pragma unroll
        for (int p = 0; p < 2; p++) {
            int b = bq * 4 + p * 2;
            unsigned long long u = acc[c][p];
            g_ph[(kc * BB + b)     * HH + c0 + c] =
                __uint_as_float((unsigned int)u);
            g_ph[(kc * BB + b + 1) * HH + c0 + c] =
                __uint_as_float((unsigned int)(u >> 32));
        }
    }
}

// ---------------- per-step: reduce hh partials, tanh, blend ------------------
__global__ void k_blend(const float* __restrict__ dec_hidden, int t)
{
    int b = blockIdx.x;
    int c = threadIdx.x;   // 0..511
    const float* hprev = (t == 0) ? (dec_hidden)
                                  : (g_h + (long long)(t - 1) * BB * HH);
    float v = g_ph[(0 * BB + b) * HH + c] + g_ph[(1 * BB + b) * HH + c]
            + g_ph[(2 * BB + b) * HH + c] + g_ph[(3 * BB + b) * HH + c];
    float hh = fast_tanh(g_gx3[b * HH + c] + v);
    float z  = g_z[b * HH + c];
    float hp = hprev[b * HH + c];
    g_h[((long long)t * BB + b) * HH + c] = z * hp + (1.f - z) * hh;
}

// ---------------- bf16 hi/lo converters --------------------------------------
__global__ void k_cvtA()
{
    int i = blockIdx.x * 256 + threadIdx.x;
    float v = g_h[i];
    __nv_bfloat16 hi = __float2bfloat16(v);
    g_Ah[i] = hi;
    g_Al[i] = __float2bfloat16(v - __bfloat162float(hi));
}

// Wo[512][32000] -> WoT[n][k] bf16 hi/lo (tiled transpose)
__global__ void k_cvtW(const float* __restrict__ Wo)
{
    __shared__ float tl[32][33];
    int n0 = blockIdx.x * 32, k0 = blockIdx.y * 32;
    int tx = threadIdx.x, ty = threadIdx.y;      // 32 x 8
#pragma unroll
    for (int r = 0; r < 4; r++) {
        int k = k0 + ty + r * 8;
        tl[ty + r * 8][tx] = Wo[(long long)k * BV + n0 + tx];
    }
    __syncthreads();
#pragma unroll
    for (int r = 0; r < 4; r++) {
        int n = n0 + ty + r * 8;
        float v = tl[tx][ty + r * 8];
        __nv_bfloat16 hi = __float2bfloat16(v);
        long long o = (long long)n * HH + k0 + tx;
        g_WTh[o] = hi;
        g_WTl[o] = __float2bfloat16(v - __bfloat162float(hi));
    }
}

// ---------------- mma.sync pred GEMM -----------------------------------------
// D[m][n] = sum_k A[m][k]*WoT[n][k], bf16 hi/lo 3-pass split, fp32 accum.
#define LDA 40   // padded row stride (bf16 elems)

#define MMA16816(cc, a, b0v, b1v) \
    asm volatile("mma.sync.aligned.m16n8k16.row.col.f32.bf16.bf16.f32 " \
        "{%0,%1,%2,%3}, {%4,%5,%6,%7}, {%8,%9}, {%0,%1,%2,%3};" \
        : "+f"((cc)[0]), "+f"((cc)[1]), "+f"((cc)[2]), "+f"((cc)[3]) \
        : "r"((a)[0]), "r"((a)[1]), "r"((a)[2]), "r"((a)[3]), \
          "r"(b0v), "r"(b1v))

__global__ __launch_bounds__(256)
void mma_pred(const float* __restrict__ bo, float* __restrict__ out)
{
    __shared__ __nv_bfloat16 Ah[128 * LDA], Al[128 * LDA];
    __shared__ __nv_bfloat16 Bh[128 * LDA], Bl[128 * LDA];

    const int tid = threadIdx.x;
    const int wid = tid >> 5, lane = tid & 31;
    const int g = lane >> 2, tq = lane & 3;
    const int wm = wid >> 1, wn = wid & 1;
    const int n0 = blockIdx.x * 128, m0 = blockIdx.y * 128;

    float acc[2][8][4];
#pragma unroll
    for (int mt = 0; mt < 2; mt++)
#pragma unroll
        for (int nt = 0; nt < 8; nt++)
#pragma unroll
            for (int c = 0; c < 4; c++) acc[mt][nt][c] = 0.f;

    for (int kc = 0; kc < 16; kc++) {
        __syncthreads();
        for (int idx = tid; idx < 1024; idx += 256) {
            int row = idx >> 3, seg = idx & 7;
            int m = m0 + row; if (m > MPRED - 1) m = MPRED - 1;
            long long ga = (long long)m * HH + kc * 32 + seg * 4;
            long long gb = (long long)(n0 + row) * HH + kc * 32 + seg * 4;
            *reinterpret_cast<uint2*>(Ah + row * LDA + seg * 4) =
                *reinterpret_cast<const uint2*>(g_Ah + ga);
            *reinterpret_cast<uint2*>(Al + row * LDA + seg * 4) =
                *reinterpret_cast<const uint2*>(g_Al + ga);
            *reinterpret_cast<uint2*>(Bh + row * LDA + seg * 4) =
                *reinterpret_cast<const uint2*>(g_WTh + gb);
            *reinterpret_cast<uint2*>(Bl + row * LDA + seg * 4) =
                *reinterpret_cast<const uint2*>(g_WTl + gb);
        }
        __syncthreads();

#pragma unroll
        for (int ks = 0; ks < 2; ks++) {
            const int ko = ks * 16;
            uint32_t afh[2][4], afl[2][4];
#pragma unroll
            for (int mt = 0; mt < 2; mt++) {
                int r0 = wm * 32 + mt * 16 + g;
                afh[mt][0] = *reinterpret_cast<uint32_t*>(Ah + r0 * LDA + ko + tq * 2);
                afh[mt][1] = *reinterpret_cast<uint32_t*>(Ah + (r0 + 8) * LDA + ko + tq * 2);
                afh[mt][2] = *reinterpret_cast<uint32_t*>(Ah + r0 * LDA + ko + 8 + tq * 2);
                afh[mt][3] = *reinterpret_cast<uint32_t*>(Ah + (r0 + 8) * LDA + ko + 8 + tq * 2);
                afl[mt][0] = *reinterpret_cast<uint32_t*>(Al + r0 * LDA + ko + tq * 2);
                afl[mt][1] = *reinterpret_cast<uint32_t*>(Al + (r0 + 8) * LDA + ko + tq * 2);
                afl[mt][2] = *reinterpret_cast<uint32_t*>(Al + r0 * LDA + ko + 8 + tq * 2);
                afl[mt][3] = *reinterpret_cast<uint32_t*>(Al + (r0 + 8) * LDA + ko + 8 + tq * 2);
            }
#pragma unroll
            for (int nt = 0; nt < 8; nt++) {
                int nr = wn * 64 + nt * 8 + g;
                uint32_t bh0 = *reinterpret_cast<uint32_t*>(Bh + nr * LDA + ko + tq * 2);
                uint32_t bh1 = *reinterpret_cast<uint32_t*>(Bh + nr * LDA + ko + 8 + tq * 2);
                uint32_t bl0 = *reinterpret_cast<uint32_t*>(Bl + nr * LDA + ko + tq * 2);
                uint32_t bl1 = *reinterpret_cast<uint32_t*>(Bl + nr * LDA + ko + 8 + tq * 2);
#pragma unroll
                for (int mt = 0; mt < 2; mt++) {
                    MMA16816(acc[mt][nt], afh[mt], bh0, bh1);
                    MMA16816(acc[mt][nt], afh[mt], bl0, bl1);
                    MMA16816(acc[mt][nt], afl[mt], bh0, bh1);
                }
            }
        }
    }

#pragma unroll
    for (int mt = 0; mt < 2; mt++) {
#pragma unroll
        for (int nt = 0; nt < 8; nt++) {
            int n = n0 + wn * 64 + nt * 8 + tq * 2;
            float b0 = bo[n], b1 = bo[n + 1];
            int m1 = m0 + wm * 32 + mt * 16 + g;
            if (m1 < MPRED) {
                int t = m1 >> 5, b = m1 & 31;
                float2 v = make_float2(acc[mt][nt][0] + b0, acc[mt][nt][1] + b1);
                *reinterpret_cast<float2*>(
                    out + (long long)b * (NSTEP * (long long)BV)
                        + (long long)t * BV + n) = v;
            }
            int m2 = m1 + 8;
            if (m2 < MPRED) {
                int t = m2 >> 5, b = m2 & 31;
                float2 v = make_float2(acc[mt][nt][2] + b0, acc[mt][nt][3] + b1);
                *reinterpret_cast<float2*>(
                    out + (long long)b * (NSTEP * (long long)BV)
                        + (long long)t * BV + n) = v;
            }
        }
    }
}

// final hidden state copy
__global__ void k_copyh(float* __restrict__ out)
{
    int i = blockIdx.x * 256 + threadIdx.x;
    out[i] = g_h[(long long)(NSTEP - 1) * BB * HH + i];
}

extern "C" void kernel_launch(void* const* d_in, const int* in_sizes, int n_in,
                              void* d_out, int out_size)
{
    const int*   dec_input  = (const int*)  d_in[0];
    const float* dec_hidden = (const float*)d_in[1];
    const float* enc_output = (const float*)d_in[2];
    const int*   dec_target = (const int*)  d_in[3];
    const float* embedding  = (const float*)d_in[4];
    const float* W1  = (const float*)d_in[5];
    const float* W2  = (const float*)d_in[6];
    const float* v_a = (const float*)d_in[7];
    const float* Wx  = (const float*)d_in[8];
    const float* Wh  = (const float*)d_in[9];
    const float* b_g = (const float*)d_in[10];
    const float* Wo  = (const float*)d_in[11];
    const float* bo  = (const float*)d_in[12];
    float* out = (float*)d_out;

    // Precompute 1: encCat = enc @ [W1 | Wx_top]   (4096 x 2048, K=512)
    gemm_k<0><<<dim3(16, 32), 256>>>(enc_output, W1, Wx, nullptr,
                                     nullptr, nullptr, nullptr, 4096, 512);
    // Precompute 2: gxemb = emb[tok] @ Wx_bot + b_g (2016 x 1536, K=256)
    gemm_k<1><<<dim3(12, 16), 256>>>(nullptr, nullptr, Wx, b_g,
                                     dec_input, dec_target, embedding,
                                     2016, 256);
    // Wo transpose + bf16 hi/lo split (independent of recurrence)
    k_cvtW<<<dim3(1000, 16), dim3(32, 8)>>>(Wo);

    // Recurrence: 63 steps x 5 kernels (k-split partials, weights read once)
    for (int t = 0; t < NSTEP; t++) {
        k_hproj  <<<dim3(4, 12), 256>>>(dec_hidden, W2, Wh, t);
        k_score  <<<dim3(16, 32), 256>>>(v_a);
        k_attnmix<<<dim3(12, 32), 128>>>(dec_hidden, t);
        k_hh     <<<dim3(4, 4), 256>>>(Wh, t);
        k_blend  <<<32, 512>>>(dec_hidden, t);
    }
    // h -> bf16 hi/lo
    k_cvtA<<<(MPRED * HH) / 256, 256>>>();
    // mma.sync pred GEMM: (2016 x 32000, K=512)
    mma_pred<<<dim3(250, 16), 256>>>(bo, out);
    // h_fin
    if ((long long)out_size >= OUT_PRED + BB * HH)
        k_copyh<<<64, 256>>>(out + OUT_PRED);
}

// round 15
// speedup vs baseline: 1.7922x; 1.7922x over previous
#include <cuda_runtime.h>
#include <cuda_bf16.h>
#include <cstdint>

// Problem constants
#define BV     32000
#define EE     256
#define HH     512
#define SS     128
#define TT     64
#define BB     32
#define NSTEP  63
#define H3     1536
#define OUT_PRED (64512000LL)
#define MPRED  2016            // 63*32 rows of h

// ---------------- scratch ----------------------------------------------------
__device__ float g_encCat[4096 * 2048];   // [b*128+s][0:512)=enc@W1, [512:2048)=enc@Wx_top
__device__ float g_gxemb [NSTEP * BB * H3];
__device__ float g_h     [NSTEP * BB * HH];
__device__ float g_pp    [4 * BB * H3];   // hproj partials: vcols 0..511=h@W2, 512..1535=h@Wh_zr
__device__ float g_ph    [4 * BB * HH];   // rh@Wh3 partials
__device__ float g_score [BB * SS];
__device__ float g_z     [BB * HH];
__device__ float g_rh    [BB * HH];
__device__ float g_gx3   [BB * HH];
// bf16 hi/lo operands for the mma pred GEMM
__device__ __nv_bfloat16 g_Ah [MPRED * HH];
__device__ __nv_bfloat16 g_Al [MPRED * HH];
__device__ __nv_bfloat16 g_WTh[(long long)BV * HH];   // WoT[n][k] hi
__device__ __nv_bfloat16 g_WTl[(long long)BV * HH];   // WoT[n][k] lo

// ---------------- helpers ----------------------------------------------------
__device__ __forceinline__ unsigned long long dup2(float b) {
    unsigned long long r;
    unsigned int u = __float_as_uint(b);
    asm("mov.b64 %0, {%1, %1};" : "=l"(r) : "r"(u));
    return r;
}
__device__ __forceinline__ void fma2(unsigned long long& d,
                                     unsigned long long a,
                                     unsigned long long b) {
    asm("fma.rn.f32x2 %0, %1, %2, %3;" : "=l"(d) : "l"(a), "l"(b), "l"(d));
}
__device__ __forceinline__ float fast_tanh(float x) {
    float e = __expf(2.0f * x);
    return 1.0f - 2.0f / (e + 1.0f);
}
__device__ __forceinline__ float fast_sig(float x) {
    return 1.0f / (1.0f + __expf(-x));
}
__device__ __forceinline__ float tanh_approx(float x) {
    float y;
    asm("tanh.approx.f32 %0, %1;" : "=f"(y) : "f"(x));
    return y;
}
__device__ __forceinline__ float ppsum(int b, int col) {
    return g_pp[(0 * BB + b) * H3 + col] + g_pp[(1 * BB + b) * H3 + col]
         + g_pp[(2 * BB + b) * H3 + col] + g_pp[(3 * BB + b) * H3 + col];
}

// ---------------- generic 128x128 tiled fp32 GEMM (precompute only) ----------
// MODE 0: C=g_encCat : A=enc(4096x512),         B=[W1 | Wx_top](512x2048)
// MODE 1: C=g_gxemb  : A=emb[tok(m)](2016x256), B=Wx_bot(256x1536), +b_g
template<int MODE>
__global__ __launch_bounds__(256, 2)
void gemm_k(const float* __restrict__ A,  const float* __restrict__ W1,
            const float* __restrict__ Wx, const float* __restrict__ bias,
            const int*   __restrict__ dinp, const int* __restrict__ dtgt,
            const float* __restrict__ emb, int M, int K)
{
    __shared__ __align__(16) float As[16][132];
    __shared__ __align__(16) float Bs[16][132];

    const int tid = threadIdx.x;
    const int tx = tid & 15;
    const int ty = tid >> 4;
    const int bn = blockIdx.x, bm = blockIdx.y;

    unsigned long long acc[4][8];
#pragma unroll
    for (int i = 0; i < 4; i++)
#pragma unroll
        for (int j = 0; j < 8; j++) acc[i][j] = 0ULL;

    const int nTiles = K >> 4;
    for (int kt = 0; kt < nTiles; ++kt) {
#pragma unroll
        for (int q = 0; q < 2; q++) {
            int l = tid * 2 + q;
            int r = l >> 2;
            int cseg = l & 3;
            int rowg = bm * 128 + r; if (rowg > M - 1) rowg = M - 1;
            const float* ap;
            if (MODE == 1) {
                int t = rowg >> 5, b = rowg & 31;
                int tok = (t == 0) ? dinp[b] : dtgt[b * TT + t];
                ap = emb + (long long)tok * EE;
            } else {
                ap = A + (long long)rowg * K;
            }
            float4 v = *reinterpret_cast<const float4*>(ap + kt * 16 + cseg * 4);
            As[cseg * 4 + 0][r] = v.x; As[cseg * 4 + 1][r] = v.y;
            As[cseg * 4 + 2][r] = v.z; As[cseg * 4 + 3][r] = v.w;
            int kr = l >> 5;
            int nseg = l & 31;
            int kg = kt * 16 + kr;
            int n = bn * 128 + nseg * 4;
            const float* bp;
            if (MODE == 0) {
                bp = (n < 512) ? (W1 + (long long)kg * 512 + n)
                               : (Wx + (long long)kg * H3 + (n - 512));
            } else {
                bp = Wx + (long long)(512 + kg) * H3 + n;
            }
            *reinterpret_cast<float4*>(&Bs[kr][nseg * 4]) =
                *reinterpret_cast<const float4*>(bp);
        }
        __syncthreads();
#pragma unroll
        for (int k = 0; k < 16; k++) {
            const unsigned long long* arow =
                reinterpret_cast<const unsigned long long*>(&As[k][0]);
            unsigned long long a0 = arow[ty * 4 + 0];
            unsigned long long a1 = arow[ty * 4 + 1];
            unsigned long long a2 = arow[ty * 4 + 2];
            unsigned long long a3 = arow[ty * 4 + 3];
            float4 b0 = *reinterpret_cast<const float4*>(&Bs[k][tx * 4]);
            float4 b1 = *reinterpret_cast<const float4*>(&Bs[k][64 + tx * 4]);
            float bf[8] = {b0.x, b0.y, b0.z, b0.w, b1.x, b1.y, b1.z, b1.w};
#pragma unroll
            for (int j = 0; j < 8; j++) {
                unsigned long long dj = dup2(bf[j]);
                fma2(acc[0][j], a0, dj);
                fma2(acc[1][j], a1, dj);
                fma2(acc[2][j], a2, dj);
                fma2(acc[3][j], a3, dj);
            }
        }
        __syncthreads();
    }

    const int nA = bn * 128 + tx * 4;
    const int nB2 = nA + 64;
#pragma unroll
    for (int i2 = 0; i2 < 4; i2++) {
#pragma unroll
        for (int p = 0; p < 2; p++) {
            int m = bm * 128 + ty * 8 + i2 * 2 + p;
            if (m >= M) continue;
            float vals[8];
#pragma unroll
            for (int j = 0; j < 8; j++) {
                unsigned long long u = acc[i2][j];
                unsigned int w = (p == 0) ? (unsigned int)u
                                          : (unsigned int)(u >> 32);
                vals[j] = __uint_as_float(w);
            }
            if (MODE == 0) {
                float* cp = g_encCat + (long long)m * 2048;
                *reinterpret_cast<float4*>(cp + nA) =
                    make_float4(vals[0], vals[1], vals[2], vals[3]);
                *reinterpret_cast<float4*>(cp + nB2) =
                    make_float4(vals[4], vals[5], vals[6], vals[7]);
            } else {
                float* cp = g_gxemb + (long long)m * H3;
                float4 ba = *reinterpret_cast<const float4*>(bias + nA);
                float4 bb = *reinterpret_cast<const float4*>(bias + nB2);
                *reinterpret_cast<float4*>(cp + nA) =
                    make_float4(vals[0] + ba.x, vals[1] + ba.y,
                                vals[2] + ba.z, vals[3] + ba.w);
                *reinterpret_cast<float4*>(cp + nB2) =
                    make_float4(vals[4] + bb.x, vals[5] + bb.y,
                                vals[6] + bb.z, vals[7] + bb.w);
            }
        }
    }
}

// ---------------- per-step: hproj partials (R13 mapping + 4-way k split) -----
// grid (12 cchunk, 32 b, 4 kc), 128 thr. One thread per output col;
// coalesced scalar weight reads; 128-iter k loop per block.
__global__ void k_hproj(const float* __restrict__ dec_hidden,
                        const float* __restrict__ W2,
                        const float* __restrict__ Wh, int t)
{
    int b = blockIdx.y;
    int kc = blockIdx.z;
    int kbase = kc * 128;
    int c = blockIdx.x * 128 + threadIdx.x;  // 0..1535
    const float* h = (t == 0) ? (dec_hidden + b * HH)
                              : (g_h + ((long long)(t - 1) * BB + b) * HH);
    __shared__ float hs[128];
    if (threadIdx.x < 128) hs[threadIdx.x] = h[kbase + threadIdx.x];
    __syncthreads();
    const float* wcol; long long ldw;
    if (c < 512) { wcol = W2 + c;         ldw = 512; }
    else         { wcol = Wh + (c - 512); ldw = H3;  }
    wcol += (long long)kbase * ldw;
    float a0 = 0.f, a1 = 0.f, a2 = 0.f, a3 = 0.f;
#pragma unroll 8
    for (int k = 0; k < 128; k += 4) {
        a0 += hs[k + 0] * wcol[(k + 0) * ldw];
        a1 += hs[k + 1] * wcol[(k + 1) * ldw];
        a2 += hs[k + 2] * wcol[(k + 2) * ldw];
        a3 += hs[k + 3] * wcol[(k + 3) * ldw];
    }
    float r = (a0 + a1) + (a2 + a3);
    // vcol: c<512 -> 0..511 (hW2); c>=512 -> 512..1535 (ghzr)
    g_pp[(kc * BB + b) * H3 + c] = r;
}

// ---------------- per-step: scores (reduce partials inline) ------------------
__global__ void k_score(const float* __restrict__ v_a)
{
    int b = blockIdx.y;
    int warp = threadIdx.x >> 5, lane = threadIdx.x & 31;
    int s = blockIdx.x * 8 + warp;
    __shared__ float hv[HH], vv[HH];
    for (int i = threadIdx.x; i < HH; i += 256) {
        hv[i] = ppsum(b, i);          // hW2 = sum of 4 k-partials
        vv[i] = v_a[i];
    }
    __syncthreads();
    const float* e = g_encCat + ((long long)b * SS + s) * 2048;
    float sum = 0.f;
#pragma unroll
    for (int i = 0; i < 16; i++) {
        int a = i * 32 + lane;
        sum += tanh_approx(e[a] + hv[a]) * vv[a];
    }
#pragma unroll
    for (int o = 16; o > 0; o >>= 1) sum += __shfl_xor_sync(0xffffffffu, sum, o);
    if (lane == 0) g_score[b * SS + s] = sum;
}

// ---------------- per-step: softmax + mix + gates ----------------------------
__global__ void k_attnmix(const float* __restrict__ dec_hidden, int t)
{
    int b = blockIdx.y;
    int tidx = threadIdx.x;
    int j = blockIdx.x * 128 + tidx;
    __shared__ float attn[SS];
    __shared__ float red[SS];

    float sc = g_score[b * SS + tidx];
    red[tidx] = sc; __syncthreads();
    for (int o = 64; o > 0; o >>= 1) {
        if (tidx < o) red[tidx] = fmaxf(red[tidx], red[tidx + o]);
        __syncthreads();
    }
    float mx = red[0]; __syncthreads();
    float ex = __expf(sc - mx);
    red[tidx] = ex; __syncthreads();
    for (int o = 64; o > 0; o >>= 1) {
        if (tidx < o) red[tidx] += red[tidx + o];
        __syncthreads();
    }
    attn[tidx] = ex / red[0];
    __syncthreads();

    const float* base = g_encCat + (long long)b * SS * 2048 + 512 + j;
    float acc = 0.f;
#pragma unroll 8
    for (int s = 0; s < SS; s++) acc += attn[s] * base[(long long)s * 2048];
    acc += g_gxemb[((long long)t * BB + b) * H3 + j];

    const float* h = (t == 0) ? (dec_hidden + b * HH)
                              : (g_h + ((long long)(t - 1) * BB + b) * HH);
    if (j < 512) {
        g_z[b * HH + j] = fast_sig(acc + ppsum(b, 512 + j));
    } else if (j < 1024) {
        int jj = j - 512;
        float rr = fast_sig(acc + ppsum(b, 512 + j));
        g_rh[b * HH + jj] = rr * h[jj];
    } else {
        g_gx3[b * HH + (j - 1024)] = acc;
    }
}

// ---------------- per-step: hh partials (R13 mapping + 4-way k split) --------
// grid (4 cchunk, 32 b, 4 kc), 128 thr.
__global__ void k_hh(const float* __restrict__ Wh, int t)
{
    int b = blockIdx.y;
    int kc = blockIdx.z;
    int kbase = kc * 128;
    int j = blockIdx.x * 128 + threadIdx.x;  // 0..511
    __shared__ float rs[128];
    if (threadIdx.x < 128) rs[threadIdx.x] = g_rh[b * HH + kbase + threadIdx.x];
    __syncthreads();
    const float* wc = Wh + 1024 + j + (long long)kbase * H3;
    float a0 = 0.f, a1 = 0.f, a2 = 0.f, a3 = 0.f;
#pragma unroll 8
    for (int k = 0; k < 128; k += 4) {
        a0 += rs[k + 0] * wc[(long long)(k + 0) * H3];
        a1 += rs[k + 1] * wc[(long long)(k + 1) * H3];
        a2 += rs[k + 2] * wc[(long long)(k + 2) * H3];
        a3 += rs[k + 3] * wc[(long long)(k + 3) * H3];
    }
    g_ph[(kc * BB + b) * HH + j] = (a0 + a1) + (a2 + a3);
}

// ---------------- per-step: reduce hh partials, tanh, blend ------------------
__global__ void k_blend(const float* __restrict__ dec_hidden, int t)
{
    int b = blockIdx.x;
    int c = threadIdx.x;   // 0..511
    const float* hprev = (t == 0) ? (dec_hidden)
                                  : (g_h + (long long)(t - 1) * BB * HH);
    float v = g_ph[(0 * BB + b) * HH + c] + g_ph[(1 * BB + b) * HH + c]
            + g_ph[(2 * BB + b) * HH + c] + g_ph[(3 * BB + b) * HH + c];
    float hh = fast_tanh(g_gx3[b * HH + c] + v);
    float z  = g_z[b * HH + c];
    float hp = hprev[b * HH + c];
    g_h[((long long)t * BB + b) * HH + c] = z * hp + (1.f - z) * hh;
}

// ---------------- bf16 hi/lo converters --------------------------------------
__global__ void k_cvtA()
{
    int i = blockIdx.x * 256 + threadIdx.x;
    float v = g_h[i];
    __nv_bfloat16 hi = __float2bfloat16(v);
    g_Ah[i] = hi;
    g_Al[i] = __float2bfloat16(v - __bfloat162float(hi));
}

// Wo[512][32000] -> WoT[n][k] bf16 hi/lo (tiled transpose)
__global__ void k_cvtW(const float* __restrict__ Wo)
{
    __shared__ float tl[32][33];
    int n0 = blockIdx.x * 32, k0 = blockIdx.y * 32;
    int tx = threadIdx.x, ty = threadIdx.y;      // 32 x 8
#pragma unroll
    for (int r = 0; r < 4; r++) {
        int k = k0 + ty + r * 8;
        tl[ty + r * 8][tx] = Wo[(long long)k * BV + n0 + tx];
    }
    __syncthreads();
#pragma unroll
    for (int r = 0; r < 4; r++) {
        int n = n0 + ty + r * 8;
        float v = tl[tx][ty + r * 8];
        __nv_bfloat16 hi = __float2bfloat16(v);
        long long o = (long long)n * HH + k0 + tx;
        g_WTh[o] = hi;
        g_WTl[o] = __float2bfloat16(v - __bfloat162float(hi));
    }
}

// ---------------- mma.sync pred GEMM -----------------------------------------
// D[m][n] = sum_k A[m][k]*WoT[n][k], bf16 hi/lo 3-pass split, fp32 accum.
#define LDA 40   // padded row stride (bf16 elems)

#define MMA16816(cc, a, b0v, b1v) \
    asm volatile("mma.sync.aligned.m16n8k16.row.col.f32.bf16.bf16.f32 " \
        "{%0,%1,%2,%3}, {%4,%5,%6,%7}, {%8,%9}, {%0,%1,%2,%3};" \
        : "+f"((cc)[0]), "+f"((cc)[1]), "+f"((cc)[2]), "+f"((cc)[3]) \
        : "r"((a)[0]), "r"((a)[1]), "r"((a)[2]), "r"((a)[3]), \
          "r"(b0v), "r"(b1v))

__global__ __launch_bounds__(256)
void mma_pred(const float* __restrict__ bo, float* __restrict__ out)
{
    __shared__ __nv_bfloat16 Ah[128 * LDA], Al[128 * LDA];
    __shared__ __nv_bfloat16 Bh[128 * LDA], Bl[128 * LDA];

    const int tid = threadIdx.x;
    const int wid = tid >> 5, lane = tid & 31;
    const int g = lane >> 2, tq = lane & 3;
    const int wm = wid >> 1, wn = wid & 1;
    const int n0 = blockIdx.x * 128, m0 = blockIdx.y * 128;

    float acc[2][8][4];
#pragma unroll
    for (int mt = 0; mt < 2; mt++)
#pragma unroll
        for (int nt = 0; nt < 8; nt++)
#pragma unroll
            for (int c = 0; c < 4; c++) acc[mt][nt][c] = 0.f;

    for (int kc = 0; kc < 16; kc++) {
        __syncthreads();
        for (int idx = tid; idx < 1024; idx += 256) {
            int row = idx >> 3, seg = idx & 7;
            int m = m0 + row; if (m > MPRED - 1) m = MPRED - 1;
            long long ga = (long long)m * HH + kc * 32 + seg * 4;
            long long gb = (long long)(n0 + row) * HH + kc * 32 + seg * 4;
            *reinterpret_cast<uint2*>(Ah + row * LDA + seg * 4) =
                *reinterpret_cast<const uint2*>(g_Ah + ga);
            *reinterpret_cast<uint2*>(Al + row * LDA + seg * 4) =
                *reinterpret_cast<const uint2*>(g_Al + ga);
            *reinterpret_cast<uint2*>(Bh + row * LDA + seg * 4) =
                *reinterpret_cast<const uint2*>(g_WTh + gb);
            *reinterpret_cast<uint2*>(Bl + row * LDA + seg * 4) =
                *reinterpret_cast<const uint2*>(g_WTl + gb);
        }
        __syncthreads();

#pragma unroll
        for (int ks = 0; ks < 2; ks++) {
            const int ko = ks * 16;
            uint32_t afh[2][4], afl[2][4];
#pragma unroll
            for (int mt = 0; mt < 2; mt++) {
                int r0 = wm * 32 + mt * 16 + g;
                afh[mt][0] = *reinterpret_cast<uint32_t*>(Ah + r0 * LDA + ko + tq * 2);
                afh[mt][1] = *reinterpret_cast<uint32_t*>(Ah + (r0 + 8) * LDA + ko + tq * 2);
                afh[mt][2] = *reinterpret_cast<uint32_t*>(Ah + r0 * LDA + ko + 8 + tq * 2);
                afh[mt][3] = *reinterpret_cast<uint32_t*>(Ah + (r0 + 8) * LDA + ko + 8 + tq * 2);
                afl[mt][0] = *reinterpret_cast<uint32_t*>(Al + r0 * LDA + ko + tq * 2);
                afl[mt][1] = *reinterpret_cast<uint32_t*>(Al + (r0 + 8) * LDA + ko + tq * 2);
                afl[mt][2] = *reinterpret_cast<uint32_t*>(Al + r0 * LDA + ko + 8 + tq * 2);
                afl[mt][3] = *reinterpret_cast<uint32_t*>(Al + (r0 + 8) * LDA + ko + 8 + tq * 2);
            }
#pragma unroll
            for (int nt = 0; nt < 8; nt++) {
                int nr = wn * 64 + nt * 8 + g;
                uint32_t bh0 = *reinterpret_cast<uint32_t*>(Bh + nr * LDA + ko + tq * 2);
                uint32_t bh1 = *reinterpret_cast<uint32_t*>(Bh + nr * LDA + ko + 8 + tq * 2);
                uint32_t bl0 = *reinterpret_cast<uint32_t*>(Bl + nr * LDA + ko + tq * 2);
                uint32_t bl1 = *reinterpret_cast<uint32_t*>(Bl + nr * LDA + ko + 8 + tq * 2);
#pragma unroll
                for (int mt = 0; mt < 2; mt++) {
                    MMA16816(acc[mt][nt], afh[mt], bh0, bh1);
                    MMA16816(acc[mt][nt], afh[mt], bl0, bl1);
                    MMA16816(acc[mt][nt], afl[mt], bh0, bh1);
                }
            }
        }
    }

#pragma unroll
    for (int mt = 0; mt < 2; mt++) {
#pragma unroll
        for (int nt = 0; nt < 8; nt++) {
            int n = n0 + wn * 64 + nt * 8 + tq * 2;
            float b0 = bo[n], b1 = bo[n + 1];
            int m1 = m0 + wm * 32 + mt * 16 + g;
            if (m1 < MPRED) {
                int t = m1 >> 5, b = m1 & 31;
                float2 v = make_float2(acc[mt][nt][0] + b0, acc[mt][nt][1] + b1);
                *reinterpret_cast<float2*>(
                    out + (long long)b * (NSTEP * (long long)BV)
                        + (long long)t * BV + n) = v;
            }
            int m2 = m1 + 8;
            if (m2 < MPRED) {
                int t = m2 >> 5, b = m2 & 31;
                float2 v = make_float2(acc[mt][nt][2] + b0, acc[mt][nt][3] + b1);
                *reinterpret_cast<float2*>(
                    out + (long long)b * (NSTEP * (long long)BV)
                        + (long long)t * BV + n) = v;
            }
        }
    }
}

// final hidden state copy
__global__ void k_copyh(float* __restrict__ out)
{
    int i = blockIdx.x * 256 + threadIdx.x;
    out[i] = g_h[(long long)(NSTEP - 1) * BB * HH + i];
}

extern "C" void kernel_launch(void* const* d_in, const int* in_sizes, int n_in,
                              void* d_out, int out_size)
{
    const int*   dec_input  = (const int*)  d_in[0];
    const float* dec_hidden = (const float*)d_in[1];
    const float* enc_output = (const float*)d_in[2];
    const int*   dec_target = (const int*)  d_in[3];
    const float* embedding  = (const float*)d_in[4];
    const float* W1  = (const float*)d_in[5];
    const float* W2  = (const float*)d_in[6];
    const float* v_a = (const float*)d_in[7];
    const float* Wx  = (const float*)d_in[8];
    const float* Wh  = (const float*)d_in[9];
    const float* b_g = (const float*)d_in[10];
    const float* Wo  = (const float*)d_in[11];
    const float* bo  = (const float*)d_in[12];
    float* out = (float*)d_out;

    // Precompute 1: encCat = enc @ [W1 | Wx_top]   (4096 x 2048, K=512)
    gemm_k<0><<<dim3(16, 32), 256>>>(enc_output, W1, Wx, nullptr,
                                     nullptr, nullptr, nullptr, 4096, 512);
    // Precompute 2: gxemb = emb[tok] @ Wx_bot + b_g (2016 x 1536, K=256)
    gemm_k<1><<<dim3(12, 16), 256>>>(nullptr, nullptr, Wx, b_g,
                                     dec_input, dec_target, embedding,
                                     2016, 256);
    // Wo transpose + bf16 hi/lo split (independent of recurrence)
    k_cvtW<<<dim3(1000, 16), dim3(32, 8)>>>(Wo);

    // Recurrence: 63 steps (k-split partials with FULL grids)
    for (int t = 0; t < NSTEP; t++) {
        k_hproj  <<<dim3(12, 32, 4), 128>>>(dec_hidden, W2, Wh, t);
        k_score  <<<dim3(16, 32), 256>>>(v_a);
        k_attnmix<<<dim3(12, 32), 128>>>(dec_hidden, t);
        k_hh     <<<dim3(4, 32, 4), 128>>>(Wh, t);
        k_blend  <<<32, 512>>>(dec_hidden, t);
    }
    // h -> bf16 hi/lo
    k_cvtA<<<(MPRED * HH) / 256, 256>>>();
    // mma.sync pred GEMM: (2016 x 32000, K=512)
    mma_pred<<<dim3(250, 16), 256>>>(bo, out);
    // h_fin
    if ((long long)out_size >= OUT_PRED + BB * HH)
        k_copyh<<<64, 256>>>(out + OUT_PRED);
}